// round 14
// baseline (speedup 1.0000x reference)
#include <cuda_runtime.h>
#include <cuda_fp16.h>
#include <cstdint>
#include <cstddef>

// ---------------- constants ----------------
#define BB 1024
#define XDIM 62
#define TWIN 10
#define INCH 128
#define MIDD 256
#define OUTD 512
#define KTOT 7936          // 62*128
#define SPLITZ 8

typedef __half h16;

// GEMM smem: 3 stages x (128x40) fp16 for A and B
#define GSTG 3
#define GROW 40
#define GEMM_SMEM (GSTG * 128 * GROW * 2 * (int)sizeof(h16))

// region permutation (concatenation of REGIONS index lists; partitions 0..61)
__constant__ int c_perm[62] = {
    0,1,2,3,4,
    5,6,7,14,15,16,
    8,9,10,17,18,19,
    11,12,13,20,21,22,
    23,24,25,32,33,34,
    26,27,28,35,36,37,
    29,30,31,38,39,40,
    41,42,43,50,51,57,
    44,45,46,52,53,54,58,59,60,
    47,48,49,55,56,61};
__constant__ int c_koff[10] = {0,640,1408,2176,2944,3712,4480,5248,6016,7168};
__constant__ int c_L[10]    = {5,6,6,6,6,6,6,6,9,6};

// ---------------- scratch (device globals; no allocation allowed) ----------------
__device__ h16   d_gcat[BB*XDIM*384];      // [g | Ag | A2g]  fp16 [M][K]
__device__ h16   d_g1[BB*XDIM*512];        // cheby1 out fp16
__device__ float d_wTf[KTOT*256];          // fp32 [k][m] staging
__device__ h16   d_wrT[256*KTOT];          // fp16 [m][k]
__device__ h16   d_c1T[512*384];           // cheby1_w^T fp16 [N][K]
__device__ h16   d_c2T[512*768];
__device__ h16   d_w1T[512*36864];
__device__ h16   d_w2T[256*512];
__device__ h16   d_g2cat[BB*10*768];       // [g2in | A1 g2in | A1^2 g2in] fp16
__device__ h16   d_g2[BB*10*512];
__device__ h16   d_outb[BB*72*512];
__device__ float d_part[SPLITZ*BB*512];
__device__ float d_h1[BB*512];
__device__ h16   d_h1b[BB*512];
__device__ float d_h2[BB*256];
__device__ float d_A2[62*62];
__device__ float d_A1s[100];
__device__ float d_mean1[512], d_rstd1[512];
__device__ float d_mean2[256], d_rstd2[256];

// ---------------- ptx helpers ----------------
__device__ __forceinline__ uint32_t smem_u32(const void* p) {
    return (uint32_t)__cvta_generic_to_shared(p);
}
__device__ __forceinline__ void cpasync16(uint32_t s, const void* g) {
    asm volatile("cp.async.cg.shared.global [%0], [%1], 16;" :: "r"(s), "l"(g));
}
__device__ __forceinline__ void cp_commit() {
    asm volatile("cp.async.commit_group;");
}
__device__ __forceinline__ void cp_wait1() {
    asm volatile("cp.async.wait_group 1;");
}

__device__ __forceinline__ void mma16(float* d, const uint32_t* a, uint32_t b0, uint32_t b1) {
    asm volatile(
        "mma.sync.aligned.m16n8k16.row.col.f32.f16.f16.f32 "
        "{%0,%1,%2,%3},{%4,%5,%6,%7},{%8,%9},{%0,%1,%2,%3};\n"
        : "+f"(d[0]), "+f"(d[1]), "+f"(d[2]), "+f"(d[3])
        : "r"(a[0]), "r"(a[1]), "r"(a[2]), "r"(a[3]), "r"(b0), "r"(b1));
}

__device__ __forceinline__ void ldsm4(uint32_t& r0, uint32_t& r1, uint32_t& r2, uint32_t& r3,
                                      uint32_t addr) {
    asm volatile("ldmatrix.sync.aligned.m8n8.x4.shared.b16 {%0,%1,%2,%3}, [%4];"
                 : "=r"(r0), "=r"(r1), "=r"(r2), "=r"(r3) : "r"(addr));
}

// ---------------- fp16 tensor-core GEMM (3-stage cp.async + ldmatrix) ----------------
// A: fp16 [M][lda] row-major.  B: fp16 [N][ldb] (weights transposed, K contiguous).
// REGION mode: A = d_gcat; the region gather is fused into the A cp.async source
// (each 16B chunk stays within one l since k is a multiple of 16 and k&127<=112).
// CTA tile 128x128, K-step 32, 256 threads = 8 warps (4M x 2N), warp tile 32x64.
// Single barrier per K-slice (validated R10/R11).
// grid: x = col tiles, y = row tiles, z = split-K chunk or region index.
// Requires M%128==0, N%128==0, K%32==0, K>=64.
template<bool RELU, bool BIAS, bool SPLITK, bool REGION, bool OUTH>
__global__ __launch_bounds__(256, 2)
void hgemm_k(const h16* __restrict__ A, const h16* __restrict__ Bt,
             void* __restrict__ Cv, const float* __restrict__ bias,
             int M, int N, int K, int lda, int ldb, int ldc) {
    extern __shared__ h16 smp[];
    h16 (*As)[128][GROW] = (h16(*)[128][GROW])smp;
    h16 (*Bs)[128][GROW] = (h16(*)[128][GROW])(smp + GSTG * 128 * GROW);

    int tid = threadIdx.x;

    h16*   Ch = (h16*)Cv;
    float* Cf = (float*)Cv;

    int lbase = 0;
    if (REGION) {
        int rz = blockIdx.z;
        lbase = c_koff[rz] >> 7;
        Bt   += c_koff[rz];
        Ch   += rz * 768;
        if (BIAS) bias += rz * MIDD;
        K = c_L[rz] * 128;
    }
    if (SPLITK) {
        A  += (size_t)blockIdx.z * K;
        Bt += (size_t)blockIdx.z * K;
        Cf += (size_t)blockIdx.z * (size_t)M * N;
    }

    int row0 = blockIdx.y * 128, col0 = blockIdx.x * 128;

    // gmem staging: 2 threads per 128-row, each 2x16B of A and of B per stage
    int sr = tid >> 1, ks = (tid & 1) * 16;
    const h16* Ap = A + (size_t)(row0 + sr) * lda + ks;
    const h16* Bp = Bt + (size_t)(col0 + sr) * ldb + ks;

    int lane = tid & 31, wid = tid >> 5;
    int wm = wid >> 1, wn = wid & 1;
    int g = lane >> 2, t2 = (lane & 3) * 2;

    // ldmatrix lane addressing
    int mi = lane >> 3, rowin = lane & 7;
    int a_row = wm * 32 + (mi & 1) * 8 + rowin;   // + mm*16
    int a_koff = (mi >> 1) * 8;                   // + kt
    int b_row = wn * 64 + (mi >> 1) * 8 + rowin;  // + p*16
    int b_koff = (mi & 1) * 8;                    // + kt

    float acc[2][8][4] = {};
    int nk = K >> 5;

    auto loadc = [&](int c) {
        int buf = c % GSTG;
        int ko = c << 5;
        uint32_t a_s = smem_u32(&As[buf][sr][ks]);
        uint32_t b_s = smem_u32(&Bs[buf][sr][ks]);
        if (REGION) {
            int k = ko + ks;                      // multiple of 16; (k&127) <= 112
            int l = lbase + (k >> 7);
            const h16* ga = A + ((size_t)(row0 + sr) * 62 + c_perm[l]) * 384 + (k & 127);
            cpasync16(a_s, ga);
            cpasync16(a_s + 16, ga + 8);
        } else {
            cpasync16(a_s, Ap + ko);
            cpasync16(a_s + 16, Ap + ko + 8);
        }
        cpasync16(b_s, Bp + ko);
        cpasync16(b_s + 16, Bp + ko + 8);
    };

    loadc(0); cp_commit();
    loadc(1); cp_commit();

    int cur = 0;
    for (int k = 0; k < nk; k++) {
        cp_wait1();            // stage k complete (stage k+1 may be pending)
        __syncthreads();       // all warps see stage k; fences last slice's reads

#pragma unroll
        for (int kt = 0; kt < 32; kt += 16) {
            uint32_t a[2][4];
#pragma unroll
            for (int mm = 0; mm < 2; mm++)
                ldsm4(a[mm][0], a[mm][1], a[mm][2], a[mm][3],
                      smem_u32(&As[cur][a_row + mm * 16][a_koff + kt]));
            uint32_t bfr[8][2];
#pragma unroll
            for (int p = 0; p < 4; p++)
                ldsm4(bfr[2 * p][0], bfr[2 * p][1], bfr[2 * p + 1][0], bfr[2 * p + 1][1],
                      smem_u32(&Bs[cur][b_row + p * 16][b_koff + kt]));
#pragma unroll
            for (int nn = 0; nn < 8; nn++) {
                mma16(acc[0][nn], a[0], bfr[nn][0], bfr[nn][1]);
                mma16(acc[1][nn], a[1], bfr[nn][0], bfr[nn][1]);
            }
        }

        // refill buffer (k+2)%3 == buffer of slice k-1; the top-of-iteration
        // barrier of slice k already separates those reads from this write.
        if (k + 2 < nk) loadc(k + 2);
        cp_commit();
        cur = (cur + 1 == GSTG) ? 0 : cur + 1;
    }

    // epilogue: warp tile 32x64
#pragma unroll
    for (int mm = 0; mm < 2; mm++) {
        int r = row0 + wm * 32 + mm * 16 + g;
#pragma unroll
        for (int nn = 0; nn < 8; nn++) {
            int c = col0 + wn * 64 + nn * 8 + t2;
            float v0 = acc[mm][nn][0], v1 = acc[mm][nn][1];
            float v2 = acc[mm][nn][2], v3 = acc[mm][nn][3];
            if (BIAS) {
                float q0 = bias[c], q1 = bias[c + 1];
                v0 += q0; v1 += q1; v2 += q0; v3 += q1;
            }
            if (RELU) {
                v0 = fmaxf(v0, 0.f); v1 = fmaxf(v1, 0.f);
                v2 = fmaxf(v2, 0.f); v3 = fmaxf(v3, 0.f);
            }
            if (OUTH) {
                *(__half2*)&Ch[(size_t)r * ldc + c] = __floats2half2_rn(v0, v1);
                *(__half2*)&Ch[(size_t)(r + 8) * ldc + c] = __floats2half2_rn(v2, v3);
            } else {
                *(float2*)&Cf[(size_t)r * ldc + c] = make_float2(v0, v1);
                *(float2*)&Cf[(size_t)(r + 8) * ldc + c] = make_float2(v2, v3);
            }
        }
    }
}

// ---------------- transpose + convert: fp32 [R][C] -> fp16 [C][R] ----------------
__global__ void cvtT_k(const float* __restrict__ src, h16* __restrict__ dst,
                       int R, int C) {
    __shared__ float tile[32][33];
    int rb = blockIdx.y * 32, cb = blockIdx.x * 32;
#pragma unroll
    for (int i = 0; i < 32; i += 8)
        tile[threadIdx.y + i][threadIdx.x] =
            src[(size_t)(rb + threadIdx.y + i) * C + cb + threadIdx.x];
    __syncthreads();
#pragma unroll
    for (int i = 0; i < 32; i += 8)
        dst[(size_t)(cb + threadIdx.y + i) * R + rb + threadIdx.x] =
            __float2half_rn(tile[threadIdx.x][threadIdx.y + i]);
}

// ---------------- small prep kernels ----------------
__global__ void a2_k(const float* __restrict__ A, float* __restrict__ A2) {
    int i = blockIdx.x * blockDim.x + threadIdx.x;
    if (i >= 62*62) return;
    int r = i / 62, c = i % 62;
    float s = 0.f;
    for (int m = 0; m < 62; m++) s += A[r*62+m] * A[m*62+c];
    A2[i] = s;
}

__global__ void a1sq_k(const float* __restrict__ A1, float* __restrict__ A1s) {
    int i = threadIdx.x;
    if (i >= 100) return;
    int r = i / 10, c = i % 10;
    float s = 0.f;
    for (int m = 0; m < 10; m++) s += A1[r*10+m] * A1[m*10+c];
    A1s[i] = s;
}

struct RWPtrs { const float* p[10]; };

// transpose region weights rw_i[m,c,l] -> wTf[(koff_i + l*128 + c)*256 + m]
__global__ void wt_k(RWPtrs rw, float* __restrict__ wT) {
    int e = blockIdx.x * 256 + threadIdx.x;   // < 7936*256
    int m = e & 255;
    int kidx = e >> 8;
    int i = 0;
#pragma unroll
    for (int q = 1; q < 10; q++) if (kidx >= c_koff[q]) i = q;
    int d = kidx - c_koff[i];
    int l = d >> 7, c = d & 127;
    wT[(size_t)kidx * 256 + m] = rw.p[i][(m * 128 + c) * c_L[i] + l];
}

// fused: variance(ddof=1) over TWIN + tfe einsum + exp gate -> g (slice 0, fp16)
__global__ void tfe_k(const float* __restrict__ x, const float* __restrict__ w,
                      const float* __restrict__ bvec, h16* __restrict__ gcat) {
    int bc = blockIdx.x;           // b*62 + c
    int c = bc % 62;
    int t = threadIdx.x;           // 0..127
    const float* xp = x + (size_t)bc * TWIN * INCH + t;
    float s1 = 0.f, s2 = 0.f, ws = 0.f;
#pragma unroll
    for (int i = 0; i < TWIN; i++) {
        float v = xp[(size_t)i * INCH];
        s1 += v; s2 += v * v;
        ws += v * w[c * TWIN + i];
    }
    float var = (s2 - s1 * s1 * 0.1f) * (1.f / 9.f);   // ddof=1
    float g = (ws + bvec[c]) * __expf(-var);
    gcat[(size_t)bc * 384 + t] = __float2half_rn(g);
}

// compute Ag, A^2 g into slices 1,2 of gcat (fp16 in/out, fp32 math)
__global__ void applyA_k(const float* __restrict__ A, const float* __restrict__ A2,
                         h16* __restrict__ gcat) {
    __shared__ float gs[62][128];
    int b = blockIdx.x;
    int t = threadIdx.x;   // 128
    int yy = threadIdx.y;  // 4
    for (int n = yy; n < 62; n += 4)
        gs[n][t] = __half2float(gcat[((size_t)b * 62 + n) * 384 + t]);
    __syncthreads();
#pragma unroll
    for (int base = 0; base < 64; base += 16) {
        int n = base + yy * 4;
        float s1[4] = {0,0,0,0}, s2[4] = {0,0,0,0};
        bool val[4];
#pragma unroll
        for (int q = 0; q < 4; q++) val[q] = (n + q) < 62;
        for (int m = 0; m < 62; m++) {
            float v = gs[m][t];
#pragma unroll
            for (int q = 0; q < 4; q++) {
                if (val[q]) {
                    s1[q] += A[(n + q) * 62 + m] * v;
                    s2[q] += A2[(n + q) * 62 + m] * v;
                }
            }
        }
#pragma unroll
        for (int q = 0; q < 4; q++) {
            if (val[q]) {
                gcat[((size_t)b * 62 + n + q) * 384 + 128 + t] = __float2half_rn(s1[q]);
                gcat[((size_t)b * 62 + n + q) * 384 + 256 + t] = __float2half_rn(s2[q]);
            }
        }
    }
}

// A1, A1^2 apply for cheby2 (slices 1,2 of g2cat, fp16)
__global__ void applyA1_k(const float* __restrict__ A1, const float* __restrict__ A1s,
                          h16* __restrict__ g2cat) {
    int b = blockIdx.x;
    int t = threadIdx.x;   // 256
    float v[10];
#pragma unroll
    for (int m = 0; m < 10; m++)
        v[m] = __half2float(g2cat[((size_t)b * 10 + m) * 768 + t]);
#pragma unroll
    for (int n = 0; n < 10; n++) {
        float s1 = 0.f, s2 = 0.f;
#pragma unroll
        for (int m = 0; m < 10; m++) {
            s1 += A1[n * 10 + m] * v[m];
            s2 += A1s[n * 10 + m] * v[m];
        }
        g2cat[((size_t)b * 10 + n) * 768 + 256 + t] = __float2half_rn(s1);
        g2cat[((size_t)b * 10 + n) * 768 + 512 + t] = __float2half_rn(s2);
    }
}

// ---------------- softmax gate (fp16 in, fp16 out; fast exp) ----------------
__global__ void softgate_k(const h16* __restrict__ g1, const h16* __restrict__ g2,
                           const float* __restrict__ bg, const float* __restrict__ cg,
                           h16* __restrict__ outb) {
    extern __shared__ float sm[];   // 72 * 512
    int b = blockIdx.x;
    int o = threadIdx.x;   // 512
    float Bg = *bg, Cg = *cg;
#pragma unroll 2
    for (int s = 0; s < 62; s++)
        sm[s * 512 + o] = __half2float(g1[((size_t)b * 62 + s) * 512 + o]);
#pragma unroll
    for (int s = 0; s < 10; s++)
        sm[(62 + s) * 512 + o] = __half2float(g2[((size_t)b * 10 + s) * 512 + o]);
    __syncthreads();
    float M = -1e30f, S = 0.f;
#pragma unroll 2
    for (int s = 0; s < 72; s++) {
        float a = ((s < 62) ? Bg : Cg) * sm[s * 512 + o];
        float nM = fmaxf(M, a);
        S = S * __expf(M - nM) + __expf(a - nM);
        M = nM;
    }
    float inv = 1.f / S;
#pragma unroll 2
    for (int s = 0; s < 72; s++) {
        float v = sm[s * 512 + o];
        float a = ((s < 62) ? Bg : Cg) * v;
        outb[(size_t)b * 36864 + s * 512 + o] = __float2half_rn(__expf(a - M) * inv * v);
    }
}

// ---------------- split-K reduce ----------------
__global__ void reduce_part_k(const float* __restrict__ part, float* __restrict__ out) {
    int i = blockIdx.x * 256 + threadIdx.x;   // < 1024*512
    float s = 0.f;
#pragma unroll
    for (int z = 0; z < SPLITZ; z++) s += part[(size_t)z * (BB * 512) + i];
    out[i] = s;
}

// ---------------- batch-norm stats + bn*gelu ----------------
__global__ void bnstats_k(const float* __restrict__ h, int F,
                          float* __restrict__ mean, float* __restrict__ rstd) {
    __shared__ float sh1[256], sh2[256];
    int j = blockIdx.x;
    float s1 = 0.f, s2 = 0.f;
    for (int b = threadIdx.x; b < BB; b += 256) {
        float v = h[(size_t)b * F + j];
        s1 += v; s2 += v * v;
    }
    sh1[threadIdx.x] = s1; sh2[threadIdx.x] = s2;
    __syncthreads();
    for (int o = 128; o; o >>= 1) {
        if (threadIdx.x < o) {
            sh1[threadIdx.x] += sh1[threadIdx.x + o];
            sh2[threadIdx.x] += sh2[threadIdx.x + o];
        }
        __syncthreads();
    }
    if (threadIdx.x == 0) {
        float mu = sh1[0] * (1.f / BB);
        float var = sh2[0] * (1.f / BB) - mu * mu;
        mean[j] = mu;
        rstd[j] = rsqrtf(var + 1e-5f);
    }
}

__global__ void bngelu_k(float* __restrict__ h, int F,
                         const float* __restrict__ mean, const float* __restrict__ rstd,
                         const float* __restrict__ gam, const float* __restrict__ bet,
                         h16* __restrict__ hb) {
    int i = blockIdx.x * 256 + threadIdx.x;
    int j = i % F;
    float v = (h[i] - mean[j]) * rstd[j] * gam[j] + bet[j];
    float r = 0.5f * v * (1.f + erff(v * 0.70710678118654752f));
    h[i] = r;
    if (hb) hb[i] = __float2half_rn(r);
}

// ---------------- final linear + softmax ----------------
__global__ void final_k(const float* __restrict__ h2, const float* __restrict__ w3,
                        const float* __restrict__ b3, float* __restrict__ out) {
    int b = blockIdx.x;
    int lane = threadIdx.x;   // 32
    float acc[4] = {0.f, 0.f, 0.f, 0.f};
    for (int k = lane; k < 256; k += 32) {
        float v = h2[(size_t)b * 256 + k];
#pragma unroll
        for (int j = 0; j < 4; j++) acc[j] += v * w3[k * 4 + j];
    }
#pragma unroll
    for (int off = 16; off; off >>= 1)
#pragma unroll
        for (int j = 0; j < 4; j++)
            acc[j] += __shfl_down_sync(0xffffffffu, acc[j], off);
    if (lane == 0) {
        float l[4];
#pragma unroll
        for (int j = 0; j < 4; j++) l[j] = acc[j] + b3[j];
        float m = fmaxf(fmaxf(l[0], l[1]), fmaxf(l[2], l[3]));
        float e[4], s = 0.f;
#pragma unroll
        for (int j = 0; j < 4; j++) { e[j] = __expf(l[j] - m); s += e[j]; }
        float inv = 1.f / s;
#pragma unroll
        for (int j = 0; j < 4; j++) out[b * 4 + j] = e[j] * inv;
    }
}

// ---------------- host ----------------
template<typename T>
static T* sym(const void* s) {
    void* p = nullptr;
    cudaGetSymbolAddress(&p, s);
    return (T*)p;
}

extern "C" void kernel_launch(void* const* d_in, const int* in_sizes, int n_in,
                              void* d_out, int out_size) {
    const float* x        = (const float*)d_in[0];
    const float* tfe_w    = (const float*)d_in[1];
    const float* tfe_b    = (const float*)d_in[2];
    const float* cheby1_w = (const float*)d_in[3];
    const float* A        = (const float*)d_in[4];
    const float* cheby2_w = (const float*)d_in[5];
    const float* A1       = (const float*)d_in[6];
    const float* b_gate   = (const float*)d_in[7];
    const float* c_gate   = (const float*)d_in[8];

    const float *rw[10], *region_b, *hc_w1, *bn1_g, *bn1_b;
    const float *hc_w2, *bn2_g, *bn2_b, *hc_w3, *hc_b3;

    if (in_sizes[9] == 2560) {
        region_b = (const float*)d_in[9];
        hc_w1    = (const float*)d_in[10];
        bn1_g    = (const float*)d_in[12];
        bn1_b    = (const float*)d_in[13];
        hc_w2    = (const float*)d_in[14];
        bn2_g    = (const float*)d_in[16];
        bn2_b    = (const float*)d_in[17];
        hc_w3    = (const float*)d_in[18];
        hc_b3    = (const float*)d_in[19];
        for (int i = 0; i < 10; i++) rw[i] = (const float*)d_in[20 + i];
    } else {
        for (int i = 0; i < 10; i++) rw[i] = (const float*)d_in[9 + i];
        region_b = (const float*)d_in[19];
        hc_w1    = (const float*)d_in[20];
        bn1_g    = (const float*)d_in[22];
        bn1_b    = (const float*)d_in[23];
        hc_w2    = (const float*)d_in[24];
        bn2_g    = (const float*)d_in[26];
        bn2_b    = (const float*)d_in[27];
        hc_w3    = (const float*)d_in[28];
        hc_b3    = (const float*)d_in[29];
    }

    h16*   p_gcat   = sym<h16>(d_gcat);
    h16*   p_g1     = sym<h16>(d_g1);
    float* p_wTf    = sym<float>(d_wTf);
    h16*   p_wrT    = sym<h16>(d_wrT);
    h16*   p_c1T    = sym<h16>(d_c1T);
    h16*   p_c2T    = sym<h16>(d_c2T);
    h16*   p_w1T    = sym<h16>(d_w1T);
    h16*   p_w2T    = sym<h16>(d_w2T);
    h16*   p_g2cat  = sym<h16>(d_g2cat);
    h16*   p_g2     = sym<h16>(d_g2);
    h16*   p_outb   = sym<h16>(d_outb);
    float* p_part   = sym<float>(d_part);
    float* p_h1     = sym<float>(d_h1);
    h16*   p_h1b    = sym<h16>(d_h1b);
    float* p_h2     = sym<float>(d_h2);
    float* p_A2     = sym<float>(d_A2);
    float* p_A1s    = sym<float>(d_A1s);
    float* p_mean1  = sym<float>(d_mean1);
    float* p_rstd1  = sym<float>(d_rstd1);
    float* p_mean2  = sym<float>(d_mean2);
    float* p_rstd2  = sym<float>(d_rstd2);

    static cudaStream_t s2 = nullptr;
    static cudaEvent_t ev_fork = nullptr, ev_c1 = nullptr, ev_gcat = nullptr, ev_g2 = nullptr;
    static bool attr_done = false;
    if (!attr_done) {
        cudaFuncSetAttribute(softgate_k, cudaFuncAttributeMaxDynamicSharedMemorySize,
                             72 * 512 * 4);
        cudaFuncSetAttribute(hgemm_k<true, false, false, false, true>,
                             cudaFuncAttributeMaxDynamicSharedMemorySize, GEMM_SMEM);
        cudaFuncSetAttribute(hgemm_k<false, true, false, true, true>,
                             cudaFuncAttributeMaxDynamicSharedMemorySize, GEMM_SMEM);
        cudaFuncSetAttribute(hgemm_k<false, false, true, false, false>,
                             cudaFuncAttributeMaxDynamicSharedMemorySize, GEMM_SMEM);
        cudaFuncSetAttribute(hgemm_k<false, false, false, false, false>,
                             cudaFuncAttributeMaxDynamicSharedMemorySize, GEMM_SMEM);
        cudaStreamCreateWithFlags(&s2, cudaStreamNonBlocking);
        cudaEventCreateWithFlags(&ev_fork, cudaEventDisableTiming);
        cudaEventCreateWithFlags(&ev_c1, cudaEventDisableTiming);
        cudaEventCreateWithFlags(&ev_gcat, cudaEventDisableTiming);
        cudaEventCreateWithFlags(&ev_g2, cudaEventDisableTiming);
        attr_done = true;
    }

    // fork: weight-prep chain on s2, overlapped with front-end on stream 0
    cudaEventRecord(ev_fork, 0);
    cudaStreamWaitEvent(s2, ev_fork, 0);

    cvtT_k<<<dim3(512/32, 384/32), dim3(32, 8), 0, s2>>>(cheby1_w, p_c1T, 384, 512);
    cudaEventRecord(ev_c1, s2);                    // cheby1 may start after this
    RWPtrs rwp;
    for (int i = 0; i < 10; i++) rwp.p[i] = rw[i];
    wt_k<<<KTOT, 256, 0, s2>>>(rwp, p_wTf);
    cvtT_k<<<dim3(256/32, KTOT/32), dim3(32, 8), 0, s2>>>(p_wTf, p_wrT, KTOT, 256);
    cvtT_k<<<dim3(512/32, 768/32), dim3(32, 8), 0, s2>>>(cheby2_w, p_c2T, 768, 512);
    cvtT_k<<<dim3(512/32, 36864/32), dim3(32, 8), 0, s2>>>(hc_w1, p_w1T, 36864, 512);
    cvtT_k<<<dim3(256/32, 512/32), dim3(32, 8), 0, s2>>>(hc_w2, p_w2T, 512, 256);

    // main stream: front-end fuse (concurrent with the prep chain)
    a2_k<<<16, 256>>>(A, p_A2);
    a1sq_k<<<1, 128>>>(A1, p_A1s);
    tfe_k<<<BB * XDIM, 128>>>(x, tfe_w, tfe_b, p_gcat);
    applyA_k<<<BB, dim3(128, 4)>>>(A, p_A2, p_gcat);
    cudaEventRecord(ev_gcat, 0);                   // gcat ready

    // s2: g2 branch (regions -> applyA1 -> cheby2), concurrent with cheby1.
    // Ordered after all s2 weight prep and after gcat.
    cudaStreamWaitEvent(s2, ev_gcat, 0);
    hgemm_k<false, true, false, true, true><<<dim3(2, 8, 10), 256, GEMM_SMEM, s2>>>(
        p_gcat, p_wrT, p_g2cat, region_b, 1024, 256, 0, 384, KTOT, 7680);
    applyA1_k<<<BB, 256, 0, s2>>>(A1, p_A1s, p_g2cat);
    hgemm_k<true, false, false, false, true><<<dim3(4, 80), 256, GEMM_SMEM, s2>>>(
        p_g2cat, p_c2T, p_g2, nullptr, 10240, 512, 768, 768, 768, 512);
    cudaEventRecord(ev_g2, s2);

    // main stream: cheby1 (needs only gcat + c1T), concurrent with g2 branch
    cudaStreamWaitEvent(0, ev_c1, 0);
    hgemm_k<true, false, false, false, true><<<dim3(4, 496), 256, GEMM_SMEM>>>(
        p_gcat, p_c1T, p_g1, nullptr, 63488, 512, 384, 384, 384, 512);

    // join: softgate needs g1 and g2 (transitively orders all s2 work, incl. w1T)
    cudaStreamWaitEvent(0, ev_g2, 0);

    // softmax gate -> (B, 36864) fp16
    softgate_k<<<BB, 512, 72 * 512 * 4>>>(p_g1, p_g2, b_gate, c_gate, p_outb);

    // hc_w1: (1024 x 36864) @ (36864 x 512), split-K=8 -> one full wave (256 CTAs)
    hgemm_k<false, false, true, false, false><<<dim3(4, 8, SPLITZ), 256, GEMM_SMEM>>>(
        p_outb, p_w1T, p_part, nullptr, 1024, 512, 36864 / SPLITZ, 36864, 36864, 512);
    reduce_part_k<<<2048, 256>>>(p_part, p_h1);

    bnstats_k<<<512, 256>>>(p_h1, 512, p_mean1, p_rstd1);
    bngelu_k<<<2048, 256>>>(p_h1, 512, p_mean1, p_rstd1, bn1_g, bn1_b, p_h1b);

    // hc_w2 (hc_b2 cancels in BN)
    hgemm_k<false, false, false, false, false><<<dim3(2, 8), 256, GEMM_SMEM>>>(
        p_h1b, p_w2T, p_h2, nullptr, 1024, 256, 512, 512, 512, 256);
    bnstats_k<<<256, 256>>>(p_h2, 256, p_mean2, p_rstd2);
    bngelu_k<<<1024, 256>>>(p_h2, 256, p_mean2, p_rstd2, bn2_g, bn2_b, nullptr);

    // final linear + softmax
    final_k<<<BB, 32>>>(p_h2, hc_w3, hc_b3, (float*)d_out);
}

// round 15
// speedup vs baseline: 1.4541x; 1.4541x over previous
#include <cuda_runtime.h>
#include <cuda_fp16.h>
#include <cstdint>
#include <cstddef>

// ---------------- constants ----------------
#define BB 1024
#define XDIM 62
#define TWIN 10
#define INCH 128
#define MIDD 256
#define OUTD 512
#define KTOT 7936          // 62*128
#define SPLITZ 8

typedef __half h16;

// GEMM smem: 3 stages x (128x40) fp16 for A and B
#define GSTG 3
#define GROW 40
#define GEMM_SMEM (GSTG * 128 * GROW * 2 * (int)sizeof(h16))

// region permutation (concatenation of REGIONS index lists; partitions 0..61)
__constant__ int c_perm[62] = {
    0,1,2,3,4,
    5,6,7,14,15,16,
    8,9,10,17,18,19,
    11,12,13,20,21,22,
    23,24,25,32,33,34,
    26,27,28,35,36,37,
    29,30,31,38,39,40,
    41,42,43,50,51,57,
    44,45,46,52,53,54,58,59,60,
    47,48,49,55,56,61};
__constant__ int c_koff[10] = {0,640,1408,2176,2944,3712,4480,5248,6016,7168};
__constant__ int c_L[10]    = {5,6,6,6,6,6,6,6,9,6};

// ---------------- scratch (device globals; no allocation allowed) ----------------
__device__ h16   d_gcat[BB*XDIM*384];      // [g | Ag | A2g]  fp16 [M][K]
__device__ h16   d_g1[BB*XDIM*512];        // cheby1 out fp16
__device__ float d_wTf[KTOT*256];          // fp32 [k][m] staging
__device__ h16   d_wrT[256*KTOT];          // fp16 [m][k]
__device__ h16   d_c1T[512*384];           // cheby1_w^T fp16 [N][K]
__device__ h16   d_c2T[512*768];
__device__ h16   d_w1T[512*36864];
__device__ h16   d_w2T[256*512];
__device__ h16   d_g2cat[BB*10*768];       // [g2in | A1 g2in | A1^2 g2in] fp16
__device__ h16   d_g2[BB*10*512];
__device__ h16   d_outb[BB*72*512];
__device__ float d_part[SPLITZ*BB*512];
__device__ float d_h1[BB*512];
__device__ h16   d_h1b[BB*512];
__device__ float d_h2[BB*256];
__device__ float d_A2[62*62];
__device__ float d_A1s[100];
__device__ float d_mean1[512], d_rstd1[512];
__device__ float d_mean2[256], d_rstd2[256];

// ---------------- ptx helpers ----------------
__device__ __forceinline__ uint32_t smem_u32(const void* p) {
    return (uint32_t)__cvta_generic_to_shared(p);
}
__device__ __forceinline__ void cpasync16(uint32_t s, const void* g) {
    asm volatile("cp.async.cg.shared.global [%0], [%1], 16;" :: "r"(s), "l"(g));
}
__device__ __forceinline__ void cp_commit() {
    asm volatile("cp.async.commit_group;");
}
__device__ __forceinline__ void cp_wait1() {
    asm volatile("cp.async.wait_group 1;");
}

__device__ __forceinline__ void mma16(float* d, const uint32_t* a, uint32_t b0, uint32_t b1) {
    asm volatile(
        "mma.sync.aligned.m16n8k16.row.col.f32.f16.f16.f32 "
        "{%0,%1,%2,%3},{%4,%5,%6,%7},{%8,%9},{%0,%1,%2,%3};\n"
        : "+f"(d[0]), "+f"(d[1]), "+f"(d[2]), "+f"(d[3])
        : "r"(a[0]), "r"(a[1]), "r"(a[2]), "r"(a[3]), "r"(b0), "r"(b1));
}

__device__ __forceinline__ void ldsm4(uint32_t& r0, uint32_t& r1, uint32_t& r2, uint32_t& r3,
                                      uint32_t addr) {
    asm volatile("ldmatrix.sync.aligned.m8n8.x4.shared.b16 {%0,%1,%2,%3}, [%4];"
                 : "=r"(r0), "=r"(r1), "=r"(r2), "=r"(r3) : "r"(addr));
}

// ---------------- fp16 tensor-core GEMM (3-stage cp.async + ldmatrix) ----------------
// A: fp16 [M][lda] row-major.  B: fp16 [N][ldb] (weights transposed, K contiguous).
// REGION mode: A = d_gcat; the region gather is fused into the A cp.async source
// (each 16B chunk stays within one l since k is a multiple of 16 and k&127<=112).
// CTA tile 128x128, K-step 32, 256 threads = 8 warps (4M x 2N), warp tile 32x64.
// Single barrier per K-slice (validated R10/R11).
// grid: x = col tiles, y = row tiles, z = split-K chunk or region index.
// Requires M%128==0, N%128==0, K%32==0, K>=64.
template<bool RELU, bool BIAS, bool SPLITK, bool REGION, bool OUTH>
__global__ __launch_bounds__(256, 2)
void hgemm_k(const h16* __restrict__ A, const h16* __restrict__ Bt,
             void* __restrict__ Cv, const float* __restrict__ bias,
             int M, int N, int K, int lda, int ldb, int ldc) {
    extern __shared__ h16 smp[];
    h16 (*As)[128][GROW] = (h16(*)[128][GROW])smp;
    h16 (*Bs)[128][GROW] = (h16(*)[128][GROW])(smp + GSTG * 128 * GROW);

    int tid = threadIdx.x;

    h16*   Ch = (h16*)Cv;
    float* Cf = (float*)Cv;

    int lbase = 0;
    if (REGION) {
        int rz = blockIdx.z;
        lbase = c_koff[rz] >> 7;
        Bt   += c_koff[rz];
        Ch   += rz * 768;
        if (BIAS) bias += rz * MIDD;
        K = c_L[rz] * 128;
    }
    if (SPLITK) {
        A  += (size_t)blockIdx.z * K;
        Bt += (size_t)blockIdx.z * K;
        Cf += (size_t)blockIdx.z * (size_t)M * N;
    }

    int row0 = blockIdx.y * 128, col0 = blockIdx.x * 128;

    // gmem staging: 2 threads per 128-row, each 2x16B of A and of B per stage
    int sr = tid >> 1, ks = (tid & 1) * 16;
    const h16* Ap = A + (size_t)(row0 + sr) * lda + ks;
    const h16* Bp = Bt + (size_t)(col0 + sr) * ldb + ks;

    int lane = tid & 31, wid = tid >> 5;
    int wm = wid >> 1, wn = wid & 1;
    int g = lane >> 2, t2 = (lane & 3) * 2;

    // ldmatrix lane addressing
    int mi = lane >> 3, rowin = lane & 7;
    int a_row = wm * 32 + (mi & 1) * 8 + rowin;   // + mm*16
    int a_koff = (mi >> 1) * 8;                   // + kt
    int b_row = wn * 64 + (mi >> 1) * 8 + rowin;  // + p*16
    int b_koff = (mi & 1) * 8;                    // + kt

    float acc[2][8][4] = {};
    int nk = K >> 5;

    auto loadc = [&](int c) {
        int buf = c % GSTG;
        int ko = c << 5;
        uint32_t a_s = smem_u32(&As[buf][sr][ks]);
        uint32_t b_s = smem_u32(&Bs[buf][sr][ks]);
        if (REGION) {
            int k = ko + ks;                      // multiple of 16; (k&127) <= 112
            int l = lbase + (k >> 7);
            const h16* ga = A + ((size_t)(row0 + sr) * 62 + c_perm[l]) * 384 + (k & 127);
            cpasync16(a_s, ga);
            cpasync16(a_s + 16, ga + 8);
        } else {
            cpasync16(a_s, Ap + ko);
            cpasync16(a_s + 16, Ap + ko + 8);
        }
        cpasync16(b_s, Bp + ko);
        cpasync16(b_s + 16, Bp + ko + 8);
    };

    loadc(0); cp_commit();
    loadc(1); cp_commit();

    int cur = 0;
    for (int k = 0; k < nk; k++) {
        cp_wait1();            // stage k complete (stage k+1 may be pending)
        __syncthreads();       // all warps see stage k; fences last slice's reads

#pragma unroll
        for (int kt = 0; kt < 32; kt += 16) {
            uint32_t a[2][4];
#pragma unroll
            for (int mm = 0; mm < 2; mm++)
                ldsm4(a[mm][0], a[mm][1], a[mm][2], a[mm][3],
                      smem_u32(&As[cur][a_row + mm * 16][a_koff + kt]));
            uint32_t bfr[8][2];
#pragma unroll
            for (int p = 0; p < 4; p++)
                ldsm4(bfr[2 * p][0], bfr[2 * p][1], bfr[2 * p + 1][0], bfr[2 * p + 1][1],
                      smem_u32(&Bs[cur][b_row + p * 16][b_koff + kt]));
#pragma unroll
            for (int nn = 0; nn < 8; nn++) {
                mma16(acc[0][nn], a[0], bfr[nn][0], bfr[nn][1]);
                mma16(acc[1][nn], a[1], bfr[nn][0], bfr[nn][1]);
            }
        }

        // refill buffer (k+2)%3 == buffer of slice k-1; the top-of-iteration
        // barrier of slice k already separates those reads from this write.
        if (k + 2 < nk) loadc(k + 2);
        cp_commit();
        cur = (cur + 1 == GSTG) ? 0 : cur + 1;
    }

    // epilogue: warp tile 32x64
#pragma unroll
    for (int mm = 0; mm < 2; mm++) {
        int r = row0 + wm * 32 + mm * 16 + g;
#pragma unroll
        for (int nn = 0; nn < 8; nn++) {
            int c = col0 + wn * 64 + nn * 8 + t2;
            float v0 = acc[mm][nn][0], v1 = acc[mm][nn][1];
            float v2 = acc[mm][nn][2], v3 = acc[mm][nn][3];
            if (BIAS) {
                float q0 = bias[c], q1 = bias[c + 1];
                v0 += q0; v1 += q1; v2 += q0; v3 += q1;
            }
            if (RELU) {
                v0 = fmaxf(v0, 0.f); v1 = fmaxf(v1, 0.f);
                v2 = fmaxf(v2, 0.f); v3 = fmaxf(v3, 0.f);
            }
            if (OUTH) {
                *(__half2*)&Ch[(size_t)r * ldc + c] = __floats2half2_rn(v0, v1);
                *(__half2*)&Ch[(size_t)(r + 8) * ldc + c] = __floats2half2_rn(v2, v3);
            } else {
                *(float2*)&Cf[(size_t)r * ldc + c] = make_float2(v0, v1);
                *(float2*)&Cf[(size_t)(r + 8) * ldc + c] = make_float2(v2, v3);
            }
        }
    }
}

// ---------------- transpose + convert: fp32 [R][C] -> fp16 [C][R] ----------------
__global__ void cvtT_k(const float* __restrict__ src, h16* __restrict__ dst,
                       int R, int C) {
    __shared__ float tile[32][33];
    int rb = blockIdx.y * 32, cb = blockIdx.x * 32;
#pragma unroll
    for (int i = 0; i < 32; i += 8)
        tile[threadIdx.y + i][threadIdx.x] =
            src[(size_t)(rb + threadIdx.y + i) * C + cb + threadIdx.x];
    __syncthreads();
#pragma unroll
    for (int i = 0; i < 32; i += 8)
        dst[(size_t)(cb + threadIdx.y + i) * R + rb + threadIdx.x] =
            __float2half_rn(tile[threadIdx.x][threadIdx.y + i]);
}

// ---------------- small prep kernels ----------------
__global__ void a2_k(const float* __restrict__ A, float* __restrict__ A2) {
    int i = blockIdx.x * blockDim.x + threadIdx.x;
    if (i >= 62*62) return;
    int r = i / 62, c = i % 62;
    float s = 0.f;
    for (int m = 0; m < 62; m++) s += A[r*62+m] * A[m*62+c];
    A2[i] = s;
}

__global__ void a1sq_k(const float* __restrict__ A1, float* __restrict__ A1s) {
    int i = threadIdx.x;
    if (i >= 100) return;
    int r = i / 10, c = i % 10;
    float s = 0.f;
    for (int m = 0; m < 10; m++) s += A1[r*10+m] * A1[m*10+c];
    A1s[i] = s;
}

struct RWPtrs { const float* p[10]; };

// transpose region weights rw_i[m,c,l] -> wTf[(koff_i + l*128 + c)*256 + m]
__global__ void wt_k(RWPtrs rw, float* __restrict__ wT) {
    int e = blockIdx.x * 256 + threadIdx.x;   // < 7936*256
    int m = e & 255;
    int kidx = e >> 8;
    int i = 0;
#pragma unroll
    for (int q = 1; q < 10; q++) if (kidx >= c_koff[q]) i = q;
    int d = kidx - c_koff[i];
    int l = d >> 7, c = d & 127;
    wT[(size_t)kidx * 256 + m] = rw.p[i][(m * 128 + c) * c_L[i] + l];
}

// fused: variance(ddof=1) over TWIN + tfe einsum + exp gate -> g (slice 0, fp16)
__global__ void tfe_k(const float* __restrict__ x, const float* __restrict__ w,
                      const float* __restrict__ bvec, h16* __restrict__ gcat) {
    int bc = blockIdx.x;           // b*62 + c
    int c = bc % 62;
    int t = threadIdx.x;           // 0..127
    const float* xp = x + (size_t)bc * TWIN * INCH + t;
    float s1 = 0.f, s2 = 0.f, ws = 0.f;
#pragma unroll
    for (int i = 0; i < TWIN; i++) {
        float v = xp[(size_t)i * INCH];
        s1 += v; s2 += v * v;
        ws += v * w[c * TWIN + i];
    }
    float var = (s2 - s1 * s1 * 0.1f) * (1.f / 9.f);   // ddof=1
    float g = (ws + bvec[c]) * __expf(-var);
    gcat[(size_t)bc * 384 + t] = __float2half_rn(g);
}

// compute Ag, A^2 g into slices 1,2 of gcat (fp16 in/out, fp32 math)
__global__ void applyA_k(const float* __restrict__ A, const float* __restrict__ A2,
                         h16* __restrict__ gcat) {
    __shared__ float gs[62][128];
    int b = blockIdx.x;
    int t = threadIdx.x;   // 128
    int yy = threadIdx.y;  // 4
    for (int n = yy; n < 62; n += 4)
        gs[n][t] = __half2float(gcat[((size_t)b * 62 + n) * 384 + t]);
    __syncthreads();
#pragma unroll
    for (int base = 0; base < 64; base += 16) {
        int n = base + yy * 4;
        float s1[4] = {0,0,0,0}, s2[4] = {0,0,0,0};
        bool val[4];
#pragma unroll
        for (int q = 0; q < 4; q++) val[q] = (n + q) < 62;
        for (int m = 0; m < 62; m++) {
            float v = gs[m][t];
#pragma unroll
            for (int q = 0; q < 4; q++) {
                if (val[q]) {
                    s1[q] += A[(n + q) * 62 + m] * v;
                    s2[q] += A2[(n + q) * 62 + m] * v;
                }
            }
        }
#pragma unroll
        for (int q = 0; q < 4; q++) {
            if (val[q]) {
                gcat[((size_t)b * 62 + n + q) * 384 + 128 + t] = __float2half_rn(s1[q]);
                gcat[((size_t)b * 62 + n + q) * 384 + 256 + t] = __float2half_rn(s2[q]);
            }
        }
    }
}

// A1, A1^2 apply for cheby2 (slices 1,2 of g2cat, fp16)
__global__ void applyA1_k(const float* __restrict__ A1, const float* __restrict__ A1s,
                          h16* __restrict__ g2cat) {
    int b = blockIdx.x;
    int t = threadIdx.x;   // 256
    float v[10];
#pragma unroll
    for (int m = 0; m < 10; m++)
        v[m] = __half2float(g2cat[((size_t)b * 10 + m) * 768 + t]);
#pragma unroll
    for (int n = 0; n < 10; n++) {
        float s1 = 0.f, s2 = 0.f;
#pragma unroll
        for (int m = 0; m < 10; m++) {
            s1 += A1[n * 10 + m] * v[m];
            s2 += A1s[n * 10 + m] * v[m];
        }
        g2cat[((size_t)b * 10 + n) * 768 + 256 + t] = __float2half_rn(s1);
        g2cat[((size_t)b * 10 + n) * 768 + 512 + t] = __float2half_rn(s2);
    }
}

// ---------------- softmax gate (fp16 in, fp16 out; single-exp 3-pass) ----------------
__global__ void softgate_k(const h16* __restrict__ g1, const h16* __restrict__ g2,
                           const float* __restrict__ bg, const float* __restrict__ cg,
                           h16* __restrict__ outb) {
    extern __shared__ float sm[];   // 72 * 512
    int b = blockIdx.x;
    int o = threadIdx.x;   // 512
    float Bg = *bg, Cg = *cg;
#pragma unroll 2
    for (int s = 0; s < 62; s++)
        sm[s * 512 + o] = __half2float(g1[((size_t)b * 62 + s) * 512 + o]);
#pragma unroll
    for (int s = 0; s < 10; s++)
        sm[(62 + s) * 512 + o] = __half2float(g2[((size_t)b * 10 + s) * 512 + o]);
    __syncthreads();
    // pass 1: max
    float M = -1e30f;
#pragma unroll 4
    for (int s = 0; s < 72; s++) {
        float a = ((s < 62) ? Bg : Cg) * sm[s * 512 + o];
        M = fmaxf(M, a);
    }
    // pass 2: e = exp(a-M) once; overwrite slot with e*v; accumulate S
    float S = 0.f;
#pragma unroll 2
    for (int s = 0; s < 72; s++) {
        float v = sm[s * 512 + o];
        float e = __expf(((s < 62) ? Bg : Cg) * v - M);
        S += e;
        sm[s * 512 + o] = e * v;
    }
    float inv = 1.f / S;
    // pass 3: scale + store
#pragma unroll 2
    for (int s = 0; s < 72; s++)
        outb[(size_t)b * 36864 + s * 512 + o] = __float2half_rn(sm[s * 512 + o] * inv);
}

// ---------------- split-K reduce ----------------
__global__ void reduce_part_k(const float* __restrict__ part, float* __restrict__ out) {
    int i = blockIdx.x * 256 + threadIdx.x;   // < 1024*512
    float s = 0.f;
#pragma unroll
    for (int z = 0; z < SPLITZ; z++) s += part[(size_t)z * (BB * 512) + i];
    out[i] = s;
}

// ---------------- batch-norm stats + bn*gelu ----------------
__global__ void bnstats_k(const float* __restrict__ h, int F,
                          float* __restrict__ mean, float* __restrict__ rstd) {
    __shared__ float sh1[256], sh2[256];
    int j = blockIdx.x;
    float s1 = 0.f, s2 = 0.f;
    for (int b = threadIdx.x; b < BB; b += 256) {
        float v = h[(size_t)b * F + j];
        s1 += v; s2 += v * v;
    }
    sh1[threadIdx.x] = s1; sh2[threadIdx.x] = s2;
    __syncthreads();
    for (int o = 128; o; o >>= 1) {
        if (threadIdx.x < o) {
            sh1[threadIdx.x] += sh1[threadIdx.x + o];
            sh2[threadIdx.x] += sh2[threadIdx.x + o];
        }
        __syncthreads();
    }
    if (threadIdx.x == 0) {
        float mu = sh1[0] * (1.f / BB);
        float var = sh2[0] * (1.f / BB) - mu * mu;
        mean[j] = mu;
        rstd[j] = rsqrtf(var + 1e-5f);
    }
}

__global__ void bngelu_k(float* __restrict__ h, int F,
                         const float* __restrict__ mean, const float* __restrict__ rstd,
                         const float* __restrict__ gam, const float* __restrict__ bet,
                         h16* __restrict__ hb) {
    int i = blockIdx.x * 256 + threadIdx.x;
    int j = i % F;
    float v = (h[i] - mean[j]) * rstd[j] * gam[j] + bet[j];
    float r = 0.5f * v * (1.f + erff(v * 0.70710678118654752f));
    h[i] = r;
    if (hb) hb[i] = __float2half_rn(r);
}

// ---------------- final linear + softmax ----------------
__global__ void final_k(const float* __restrict__ h2, const float* __restrict__ w3,
                        const float* __restrict__ b3, float* __restrict__ out) {
    int b = blockIdx.x;
    int lane = threadIdx.x;   // 32
    float acc[4] = {0.f, 0.f, 0.f, 0.f};
    for (int k = lane; k < 256; k += 32) {
        float v = h2[(size_t)b * 256 + k];
#pragma unroll
        for (int j = 0; j < 4; j++) acc[j] += v * w3[k * 4 + j];
    }
#pragma unroll
    for (int off = 16; off; off >>= 1)
#pragma unroll
        for (int j = 0; j < 4; j++)
            acc[j] += __shfl_down_sync(0xffffffffu, acc[j], off);
    if (lane == 0) {
        float l[4];
#pragma unroll
        for (int j = 0; j < 4; j++) l[j] = acc[j] + b3[j];
        float m = fmaxf(fmaxf(l[0], l[1]), fmaxf(l[2], l[3]));
        float e[4], s = 0.f;
#pragma unroll
        for (int j = 0; j < 4; j++) { e[j] = __expf(l[j] - m); s += e[j]; }
        float inv = 1.f / s;
#pragma unroll
        for (int j = 0; j < 4; j++) out[b * 4 + j] = e[j] * inv;
    }
}

// ---------------- host ----------------
template<typename T>
static T* sym(const void* s) {
    void* p = nullptr;
    cudaGetSymbolAddress(&p, s);
    return (T*)p;
}

extern "C" void kernel_launch(void* const* d_in, const int* in_sizes, int n_in,
                              void* d_out, int out_size) {
    const float* x        = (const float*)d_in[0];
    const float* tfe_w    = (const float*)d_in[1];
    const float* tfe_b    = (const float*)d_in[2];
    const float* cheby1_w = (const float*)d_in[3];
    const float* A        = (const float*)d_in[4];
    const float* cheby2_w = (const float*)d_in[5];
    const float* A1       = (const float*)d_in[6];
    const float* b_gate   = (const float*)d_in[7];
    const float* c_gate   = (const float*)d_in[8];

    const float *rw[10], *region_b, *hc_w1, *bn1_g, *bn1_b;
    const float *hc_w2, *bn2_g, *bn2_b, *hc_w3, *hc_b3;

    if (in_sizes[9] == 2560) {
        region_b = (const float*)d_in[9];
        hc_w1    = (const float*)d_in[10];
        bn1_g    = (const float*)d_in[12];
        bn1_b    = (const float*)d_in[13];
        hc_w2    = (const float*)d_in[14];
        bn2_g    = (const float*)d_in[16];
        bn2_b    = (const float*)d_in[17];
        hc_w3    = (const float*)d_in[18];
        hc_b3    = (const float*)d_in[19];
        for (int i = 0; i < 10; i++) rw[i] = (const float*)d_in[20 + i];
    } else {
        for (int i = 0; i < 10; i++) rw[i] = (const float*)d_in[9 + i];
        region_b = (const float*)d_in[19];
        hc_w1    = (const float*)d_in[20];
        bn1_g    = (const float*)d_in[22];
        bn1_b    = (const float*)d_in[23];
        hc_w2    = (const float*)d_in[24];
        bn2_g    = (const float*)d_in[26];
        bn2_b    = (const float*)d_in[27];
        hc_w3    = (const float*)d_in[28];
        hc_b3    = (const float*)d_in[29];
    }

    h16*   p_gcat   = sym<h16>(d_gcat);
    h16*   p_g1     = sym<h16>(d_g1);
    float* p_wTf    = sym<float>(d_wTf);
    h16*   p_wrT    = sym<h16>(d_wrT);
    h16*   p_c1T    = sym<h16>(d_c1T);
    h16*   p_c2T    = sym<h16>(d_c2T);
    h16*   p_w1T    = sym<h16>(d_w1T);
    h16*   p_w2T    = sym<h16>(d_w2T);
    h16*   p_g2cat  = sym<h16>(d_g2cat);
    h16*   p_g2     = sym<h16>(d_g2);
    h16*   p_outb   = sym<h16>(d_outb);
    float* p_part   = sym<float>(d_part);
    float* p_h1     = sym<float>(d_h1);
    h16*   p_h1b    = sym<h16>(d_h1b);
    float* p_h2     = sym<float>(d_h2);
    float* p_A2     = sym<float>(d_A2);
    float* p_A1s    = sym<float>(d_A1s);
    float* p_mean1  = sym<float>(d_mean1);
    float* p_rstd1  = sym<float>(d_rstd1);
    float* p_mean2  = sym<float>(d_mean2);
    float* p_rstd2  = sym<float>(d_rstd2);

    static cudaStream_t s2 = nullptr;
    static cudaEvent_t ev_fork = nullptr, ev_join = nullptr;
    static bool attr_done = false;
    if (!attr_done) {
        cudaFuncSetAttribute(softgate_k, cudaFuncAttributeMaxDynamicSharedMemorySize,
                             72 * 512 * 4);
        cudaFuncSetAttribute(hgemm_k<true, false, false, false, true>,
                             cudaFuncAttributeMaxDynamicSharedMemorySize, GEMM_SMEM);
        cudaFuncSetAttribute(hgemm_k<false, true, false, true, true>,
                             cudaFuncAttributeMaxDynamicSharedMemorySize, GEMM_SMEM);
        cudaFuncSetAttribute(hgemm_k<false, false, true, false, false>,
                             cudaFuncAttributeMaxDynamicSharedMemorySize, GEMM_SMEM);
        cudaFuncSetAttribute(hgemm_k<false, false, false, false, false>,
                             cudaFuncAttributeMaxDynamicSharedMemorySize, GEMM_SMEM);
        cudaStreamCreateWithFlags(&s2, cudaStreamNonBlocking);
        cudaEventCreateWithFlags(&ev_fork, cudaEventDisableTiming);
        cudaEventCreateWithFlags(&ev_join, cudaEventDisableTiming);
        attr_done = true;
    }

    // fork: weight-prep chain on s2, overlapped with front-end on stream 0
    // (R14 lesson: do NOT overlap GEMMs with GEMMs; only cheap prep with front-end)
    cudaEventRecord(ev_fork, 0);
    cudaStreamWaitEvent(s2, ev_fork, 0);

    cvtT_k<<<dim3(512/32, 384/32), dim3(32, 8), 0, s2>>>(cheby1_w, p_c1T, 384, 512);
    RWPtrs rwp;
    for (int i = 0; i < 10; i++) rwp.p[i] = rw[i];
    wt_k<<<KTOT, 256, 0, s2>>>(rwp, p_wTf);
    cvtT_k<<<dim3(256/32, KTOT/32), dim3(32, 8), 0, s2>>>(p_wTf, p_wrT, KTOT, 256);
    cvtT_k<<<dim3(512/32, 768/32), dim3(32, 8), 0, s2>>>(cheby2_w, p_c2T, 768, 512);
    cvtT_k<<<dim3(512/32, 36864/32), dim3(32, 8), 0, s2>>>(hc_w1, p_w1T, 36864, 512);
    cvtT_k<<<dim3(256/32, 512/32), dim3(32, 8), 0, s2>>>(hc_w2, p_w2T, 512, 256);
    cudaEventRecord(ev_join, s2);

    // main stream: front-end fuse (concurrent with the prep chain)
    a2_k<<<16, 256>>>(A, p_A2);
    a1sq_k<<<1, 128>>>(A1, p_A1s);
    tfe_k<<<BB * XDIM, 128>>>(x, tfe_w, tfe_b, p_gcat);
    applyA_k<<<BB, dim3(128, 4)>>>(A, p_A2, p_gcat);

    // join: everything below needs the converted weights
    cudaStreamWaitEvent(0, ev_join, 0);

    // cheby1: (63488 x 384) @ (384 x 512) + relu
    hgemm_k<true, false, false, false, true><<<dim3(4, 496), 256, GEMM_SMEM>>>(
        p_gcat, p_c1T, p_g1, nullptr, 63488, 512, 384, 384, 384, 512);

    // regions: batched 10 GEMMs (1024 x 256, K = L_i*128) + bias, A gathered
    // directly from gcat via c_perm inside the GEMM (no regbuf round-trip)
    hgemm_k<false, true, false, true, true><<<dim3(2, 8, 10), 256, GEMM_SMEM>>>(
        p_gcat, p_wrT, p_g2cat, region_b, 1024, 256, 0, 384, KTOT, 7680);

    // cheby2
    applyA1_k<<<BB, 256>>>(A1, p_A1s, p_g2cat);
    hgemm_k<true, false, false, false, true><<<dim3(4, 80), 256, GEMM_SMEM>>>(
        p_g2cat, p_c2T, p_g2, nullptr, 10240, 512, 768, 768, 768, 512);

    // softmax gate -> (B, 36864) fp16
    softgate_k<<<BB, 512, 72 * 512 * 4>>>(p_g1, p_g2, b_gate, c_gate, p_outb);

    // hc_w1: (1024 x 36864) @ (36864 x 512), split-K=8 -> one full wave (256 CTAs)
    hgemm_k<false, false, true, false, false><<<dim3(4, 8, SPLITZ), 256, GEMM_SMEM>>>(
        p_outb, p_w1T, p_part, nullptr, 1024, 512, 36864 / SPLITZ, 36864, 36864, 512);
    reduce_part_k<<<2048, 256>>>(p_part, p_h1);

    bnstats_k<<<512, 256>>>(p_h1, 512, p_mean1, p_rstd1);
    bngelu_k<<<2048, 256>>>(p_h1, 512, p_mean1, p_rstd1, bn1_g, bn1_b, p_h1b);

    // hc_w2 (hc_b2 cancels in BN)
    hgemm_k<false, false, false, false, false><<<dim3(2, 8), 256, GEMM_SMEM>>>(
        p_h1b, p_w2T, p_h2, nullptr, 1024, 256, 512, 512, 512, 256);
    bnstats_k<<<256, 256>>>(p_h2, 256, p_mean2, p_rstd2);
    bngelu_k<<<1024, 256>>>(p_h2, 256, p_mean2, p_rstd2, bn2_g, bn2_b, nullptr);

    // final linear + softmax
    final_k<<<BB, 32>>>(p_h2, hc_w3, hc_b3, (float*)d_out);
}